// round 15
// baseline (speedup 1.0000x reference)
#include <cuda_runtime.h>
#include <cstdint>

#define B    64
#define N    65536
#define CPB  4                  // CTAs per batch
#define GRID (B * CPB)          // 256, all resident (148 SMs x 2) -- proven
#define TH   512
#define QN   (N / CPB)          // 16384 points per CTA
#define QP   (QN / 2)           // 8192 pairs per CTA
#define PPT  (QN / TH)          // 32 points per thread
#define PPAIR (QP / TH)         // 16 pairs per thread
#define WQ   (QN / 32)          // 512 bitmask words per quarter (== TH)

// ---- __device__ scratch (allocation-free rule) ----
__device__ float4   g_xy4[B * N / 2];       // {x0,y0,x1,y1} per pair (32 MB)
__device__ float2   g_z2[B * N / 2];        // {z0,z1} per pair (16 MB)
__device__ float    g_pv[2 * GRID];         // partial argmax values (double-buffered)
__device__ int      g_pi[2 * GRID];         // partial argmax indices (global ids)
__device__ int      g_stage[B * N];         // per-quarter staged kept indices
__device__ int      g_qtot[GRID];           // per-quarter keep counts
__device__ unsigned g_cnt[B];               // per-batch barrier counters
__device__ unsigned g_gen[B];               // per-batch barrier generations

// Per-batch barrier among the CPB CTAs of one batch. All CTAs resident.
__device__ __forceinline__ void batch_sync(int b) {
    __syncthreads();
    if (threadIdx.x == 0) {
        __threadfence();
        const unsigned gen = atomicAdd(&g_gen[b], 0u);
        if (atomicAdd(&g_cnt[b], 1u) == CPB - 1u) {
            atomicExch(&g_cnt[b], 0u);
            __threadfence();
            atomicAdd(&g_gen[b], 1u);                 // release
        } else {
            while (atomicAdd(&g_gen[b], 0u) == gen) { __nanosleep(32); }
        }
        __threadfence();
    }
    __syncthreads();
}

// warp argmax: value desc, index asc on ties
__device__ __forceinline__ void warp_argmax(float& best, int& bi) {
    #pragma unroll
    for (int o = 16; o; o >>= 1) {
        const float v = __shfl_down_sync(0xffffffffu, best, o);
        const int   j = __shfl_down_sync(0xffffffffu, bi,   o);
        if (v > best || (v == best && j < bi)) { best = v; bi = j; }
    }
}

// block partial argmax (512 threads) -> g_pv/g_pi[buf*GRID + cta]
__device__ __forceinline__ void block_partial(float best, int bi, int buf,
                                              float* sv, int* si) {
    const int t = threadIdx.x, lane = t & 31, w = t >> 5;
    warp_argmax(best, bi);
    if (lane == 0) { sv[w] = best; si[w] = bi; }
    __syncthreads();
    if (t < 16) {
        best = sv[t]; bi = si[t];
        #pragma unroll
        for (int o = 8; o; o >>= 1) {
            const float v = __shfl_down_sync(0xffffu, best, o);
            const int   j = __shfl_down_sync(0xffffu, bi,   o);
            if (v > best || (v == best && j < bi)) { best = v; bi = j; }
        }
        if (t == 0) {
            g_pv[buf * GRID + blockIdx.x] = best;
            g_pi[buf * GRID + blockIdx.x] = bi;
        }
    }
    __syncthreads();   // sv/si reused by later phases
}

// spread low 16 bits of x into even bit positions
__device__ __forceinline__ unsigned expand16(unsigned x) {
    x &= 0xFFFFu;
    x = (x | (x << 8)) & 0x00FF00FFu;
    x = (x | (x << 4)) & 0x0F0F0F0Fu;
    x = (x | (x << 2)) & 0x33333333u;
    x = (x | (x << 1)) & 0x55555555u;
    return x;
}

// kept-rank k -> source point index, via per-quarter staging regions
__device__ __forceinline__ int rank_lookup(const int* stg, int k,
                                           int c1, int c2, int c3) {
    const int qq  = (k >= c1) + (k >= c2) + (k >= c3);
    const int cum = (qq == 0) ? 0 : (qq == 1) ? c1 : (qq == 2) ? c2 : c3;
    return stg[qq * QN + (k - cum)];
}

__global__ __launch_bounds__(TH, 2) void mega_kernel(const float* __restrict__ pts,
                                                     float* __restrict__ out) {
    const int cta  = blockIdx.x;
    const int b    = cta / CPB;
    const int q    = cta % CPB;
    const int base = q * QN;                         // batch-local start
    const float* P = pts + (size_t)b * N * 6;
    const float4* In = (const float4*)P;             // batch rows as float4s
    const int t = threadIdx.x;
    const int lane = t & 31, w = t >> 5;

    __shared__ float4   sc[4];
    __shared__ float    sv[16];
    __shared__ int      si[16];
    __shared__ int      swarp[16];
    __shared__ int      sq[CPB];
    __shared__ unsigned sw[WQ];                      // mask words (2 KB)

    // ===== Phase 0: pair-pack -> XY4/Z2 scratch + dist^2 to center 0 =======
    const float c0x = P[0], c0y = P[1], c0z = P[2];  // center 0 = point 0
    if (t == 0) sc[0] = make_float4(c0x, c0y, c0z, 0.f);
    {
        float best = -1.0f; int bi = 0;
        #pragma unroll 8
        for (int k = 0; k < PPAIR; k++) {
            const int pr = q * QP + t + k * TH;      // batch-local pair
            const int gp = b * (N / 2) + pr;         // global pair id
            const float4 f0 = In[pr * 3];            // x0 y0 z0 a0
            const float4 f1 = In[pr * 3 + 1];        // b0 c0 x1 y1
            const float4 f2 = In[pr * 3 + 2];        // z1 a1 b1 c1
            g_xy4[gp] = make_float4(f0.x, f0.y, f1.z, f1.w);
            g_z2[gp]  = make_float2(f0.z, f2.x);
            float dx = f0.x - c0x, dy = f0.y - c0y, dz = f0.z - c0z;
            const float md0 = dx * dx + dy * dy + dz * dz;
            dx = f1.z - c0x; dy = f1.w - c0y; dz = f2.x - c0z;
            const float md1 = dx * dx + dy * dy + dz * dz;
            const int gi = b * N + pr * 2;
            if (md0 > best) { best = md0; bi = gi; }     // strict >: min-index ties
            if (md1 > best) { best = md1; bi = gi + 1; }
        }
        block_partial(best, bi, /*buf=*/0, sv, si);
    }
    batch_sync(b);

    // ========== Phases 1,2: FPS steps; s==3 only resolves center 3 =========
    for (int s = 1; s <= 3; s++) {
        const int rbuf = (s - 1) & 1;                // buffer written by phase s-1
        if (t == 0) {
            float bv = g_pv[rbuf * GRID + b * CPB];
            int   bj = g_pi[rbuf * GRID + b * CPB];
            #pragma unroll
            for (int i = 1; i < CPB; i++) {
                const float v = g_pv[rbuf * GRID + b * CPB + i];
                const int   j = g_pi[rbuf * GRID + b * CPB + i];
                if (v > bv || (v == bv && j < bj)) { bv = v; bj = j; }
            }
            const float* cp = pts + (size_t)bj * 6;  // xyz of chosen point
            sc[s] = make_float4(cp[0], cp[1], cp[2], 0.f);
        }
        __syncthreads();
        if (s == 3) break;                           // all 4 centers known

        float best = -1.0f; int bi = 0;
        #pragma unroll 8
        for (int k = 0; k < PPAIR; k++) {
            const int pr = q * QP + t + k * TH;
            const int gp = b * (N / 2) + pr;
            const float4 xy = g_xy4[gp];             // 1 LDG.128 per pair
            const float2 zz = g_z2[gp];              // 1 LDG.64 per pair
            float md0 = 1e10f, md1 = 1e10f;
            for (int cc = 0; cc <= s; cc++) {
                float dx = xy.x - sc[cc].x, dy = xy.y - sc[cc].y, dz = zz.x - sc[cc].z;
                md0 = fminf(md0, dx * dx + dy * dy + dz * dz);
                dx = xy.z - sc[cc].x; dy = xy.w - sc[cc].y; dz = zz.y - sc[cc].z;
                md1 = fminf(md1, dx * dx + dy * dy + dz * dz);
            }
            const int gi = b * N + pr * 2;
            if (md0 > best) { best = md0; bi = gi; }
            if (md1 > best) { best = md1; bi = gi + 1; }
        }
        block_partial(best, bi, /*buf=*/s & 1, sv, si);
        batch_sync(b);
    }

    // ====== Phase 3: keep bitmask -> smem words (paired, bit-interleave) ===
    {
        const float4 cc0 = sc[0], cc1 = sc[1], cc2 = sc[2], cc3 = sc[3];
        #pragma unroll 8
        for (int k = 0; k < PPAIR; k++) {
            const int pr = q * QP + t + k * TH;      // lanes consecutive pairs
            const int gp = b * (N / 2) + pr;
            const float4 xy = g_xy4[gp];
            const float2 zz = g_z2[gp];
            float dx = xy.x - cc0.x, dy = xy.y - cc0.y, dz = zz.x - cc0.z;
            float md0 = fminf(1e10f, dx * dx + dy * dy + dz * dz);
            dx = xy.x - cc1.x; dy = xy.y - cc1.y; dz = zz.x - cc1.z;
            md0 = fminf(md0, dx * dx + dy * dy + dz * dz);
            dx = xy.x - cc2.x; dy = xy.y - cc2.y; dz = zz.x - cc2.z;
            md0 = fminf(md0, dx * dx + dy * dy + dz * dz);
            dx = xy.x - cc3.x; dy = xy.y - cc3.y; dz = zz.x - cc3.z;
            md0 = fminf(md0, dx * dx + dy * dy + dz * dz);

            dx = xy.z - cc0.x; dy = xy.w - cc0.y; dz = zz.y - cc0.z;
            float md1 = fminf(1e10f, dx * dx + dy * dy + dz * dz);
            dx = xy.z - cc1.x; dy = xy.w - cc1.y; dz = zz.y - cc1.z;
            md1 = fminf(md1, dx * dx + dy * dy + dz * dz);
            dx = xy.z - cc2.x; dy = xy.w - cc2.y; dz = zz.y - cc2.z;
            md1 = fminf(md1, dx * dx + dy * dy + dz * dz);
            dx = xy.z - cc3.x; dy = xy.w - cc3.y; dz = zz.y - cc3.z;
            md1 = fminf(md1, dx * dx + dy * dy + dz * dz);

            const unsigned b0 = __ballot_sync(0xffffffffu, __fsqrt_rn(md0) >= 0.2f);
            const unsigned b1 = __ballot_sync(0xffffffffu, __fsqrt_rn(md1) >= 0.2f);
            // warp covers 64 consecutive points -> 2 words, bit-interleaved
            const int wq0 = 2 * w + k * 32;                  // quarter-local word id
            if (lane == 0) sw[wq0]     = expand16(b0) | (expand16(b1) << 1);
            if (lane == 1) sw[wq0 + 1] = expand16(b0 >> 16) | (expand16(b1 >> 16) << 1);
        }
    }
    __syncthreads();                                  // block-local only

    // == Phase 4: quarter-local stable compaction into this CTA's stage region
    int nv, c1, c2, c3;                              // cumulative quarter starts
    {
        const unsigned wd = sw[t];                   // word t of this quarter
        const int cnt = __popc(wd);

        int inc = cnt;
        #pragma unroll
        for (int o = 1; o < 32; o <<= 1) {
            const int u = __shfl_up_sync(0xffffffffu, inc, o);
            if (lane >= o) inc += u;
        }
        if (lane == 31) swarp[w] = inc;
        __syncthreads();
        if (t < 16) {
            int v2 = swarp[t];
            #pragma unroll
            for (int o = 1; o < 16; o <<= 1) {
                const int u = __shfl_up_sync(0xffffu, v2, o);
                if (t >= o) v2 += u;
            }
            swarp[t] = v2;
        }
        __syncthreads();
        const int off_local = inc - cnt + (w ? swarp[w - 1] : 0);
        if (t == 0) g_qtot[cta] = swarp[15];         // publish quarter total

        // write kept indices into this CTA's own region (overlaps barrier)
        int* stq = g_stage + b * N + q * QN;
        int pos = off_local;
        const int pbase = q * QN + t * 32;           // first point of this word
        unsigned m = wd;
        while (m) { const int l2 = __ffs(m) - 1; m &= m - 1; stq[pos++] = pbase + l2; }

        batch_sync(b);                               // stage + qtot visible

        if (t < CPB) sq[t] = g_qtot[b * CPB + t];
        __syncthreads();
        c1 = sq[0]; c2 = c1 + sq[1]; c3 = c2 + sq[2];
        nv = c3 + sq[3];
    }

    // ====== Phase 5: gather with per-warp consecutive-run fast path =========
    {
        const int* stg = g_stage + (b << 16);
        #pragma unroll 1
        for (int k = 0; k < PPT / 2; k++) {
            const int jr0 = base + (w * 32 + k * TH) * 2;   // warp's first row (64 rows)
            bool fast = false; int sfirst = 0;
            if (nv > 0) {
                const int kf = jr0 % nv;
                if (kf + 63 < nv) {
                    int sA = 0, sB = 0;
                    if (lane == 0) {
                        sA = rank_lookup(stg, kf,      c1, c2, c3);
                        sB = rank_lookup(stg, kf + 63, c1, c2, c3);
                    }
                    sA = __shfl_sync(0xffffffffu, sA, 0);
                    sB = __shfl_sync(0xffffffffu, sB, 0);
                    fast = (sB - sA == 63);           // 64 consecutive sources
                    sfirst = sA;
                }
            }
            if (fast) {
                // contiguous 1536B block copy, fully coalesced float2s
                const float2* s2 = (const float2*)(pts + ((size_t)(b << 16) + sfirst) * 6);
                float2* d2 = (float2*)(out + ((size_t)b * N + jr0) * 6);
                #pragma unroll
                for (int m = 0; m < 6; m++) __stcs(&d2[m * 32 + lane], s2[m * 32 + lane]);
            } else {
                const int jr = jr0 + lane * 2;              // this lane's 2 rows
                float4* dst = (float4*)(out + ((size_t)b * N + jr) * 6);
                if (nv == 0) {
                    const float4 z4 = make_float4(0.f, 0.f, 0.f, 0.f);
                    __stcs(&dst[0], z4); __stcs(&dst[1], z4); __stcs(&dst[2], z4);
                    continue;
                }
                const int k0 = jr % nv;
                const int k1 = (k0 + 1 == nv) ? 0 : k0 + 1;
                const int s0 = rank_lookup(stg, k0, c1, c2, c3);
                const int s1 = rank_lookup(stg, k1, c1, c2, c3);
                const float* p0 = pts + ((size_t)(b << 16) + s0) * 6;
                const float* p1 = pts + ((size_t)(b << 16) + s1) * 6;
                const float2 a0 = *(const float2*)p0;
                const float2 a1 = *(const float2*)(p0 + 2);
                const float2 a2 = *(const float2*)(p0 + 4);
                const float2 b0 = *(const float2*)p1;
                const float2 b1 = *(const float2*)(p1 + 2);
                const float2 b2 = *(const float2*)(p1 + 4);
                __stcs(&dst[0], make_float4(a0.x, a0.y, a1.x, a1.y));
                __stcs(&dst[1], make_float4(a2.x, a2.y, b0.x, b0.y));
                __stcs(&dst[2], make_float4(b1.x, b1.y, b2.x, b2.y));
            }
        }
    }
}

extern "C" void kernel_launch(void* const* d_in, const int* in_sizes, int n_in,
                              void* d_out, int out_size) {
    const float* pts = (const float*)d_in[0];
    float* out = (float*)d_out;
    mega_kernel<<<GRID, TH>>>(pts, out);
}

// round 16
// speedup vs baseline: 1.0181x; 1.0181x over previous
#include <cuda_runtime.h>
#include <cstdint>

#define B    64
#define N    65536
#define CPB  4                  // CTAs per batch
#define GRID (B * CPB)          // 256, all resident (148 SMs x 2) -- proven
#define TH   512
#define QN   (N / CPB)          // 16384 points per CTA
#define QP   (QN / 2)           // 8192 pairs per CTA
#define PPT  (QN / TH)          // 32 points per thread
#define PPAIR (QP / TH)         // 16 pairs per thread
#define WQ   (QN / 32)          // 512 bitmask words per quarter (== TH)

// ---- __device__ scratch (allocation-free rule) ----
__device__ float4   g_xy4[B * N / 2];       // {x0,y0,x1,y1} per pair (32 MB)
__device__ float2   g_z2[B * N / 2];        // {z0,z1} per pair (16 MB)
__device__ float    g_pv[2 * GRID];         // partial argmax values (double-buffered)
__device__ int      g_pi[2 * GRID];         // partial argmax indices (global ids)
__device__ int      g_stage[B * N];         // per-quarter staged kept indices
__device__ int      g_qtot[GRID];           // per-quarter keep counts
__device__ unsigned g_cnt[B];               // per-batch barrier counters
__device__ unsigned g_gen[B];               // per-batch barrier generations

// Per-batch barrier among the CPB CTAs of one batch. All CTAs resident.
__device__ __forceinline__ void batch_sync(int b) {
    __syncthreads();
    if (threadIdx.x == 0) {
        __threadfence();
        const unsigned gen = atomicAdd(&g_gen[b], 0u);
        if (atomicAdd(&g_cnt[b], 1u) == CPB - 1u) {
            atomicExch(&g_cnt[b], 0u);
            __threadfence();
            atomicAdd(&g_gen[b], 1u);                 // release
        } else {
            while (atomicAdd(&g_gen[b], 0u) == gen) { __nanosleep(32); }
        }
        __threadfence();
    }
    __syncthreads();
}

// warp argmax: value desc, index asc on ties
__device__ __forceinline__ void warp_argmax(float& best, int& bi) {
    #pragma unroll
    for (int o = 16; o; o >>= 1) {
        const float v = __shfl_down_sync(0xffffffffu, best, o);
        const int   j = __shfl_down_sync(0xffffffffu, bi,   o);
        if (v > best || (v == best && j < bi)) { best = v; bi = j; }
    }
}

// block partial argmax (512 threads) -> g_pv/g_pi[buf*GRID + cta]
__device__ __forceinline__ void block_partial(float best, int bi, int buf,
                                              float* sv, int* si) {
    const int t = threadIdx.x, lane = t & 31, w = t >> 5;
    warp_argmax(best, bi);
    if (lane == 0) { sv[w] = best; si[w] = bi; }
    __syncthreads();
    if (t < 16) {
        best = sv[t]; bi = si[t];
        #pragma unroll
        for (int o = 8; o; o >>= 1) {
            const float v = __shfl_down_sync(0xffffu, best, o);
            const int   j = __shfl_down_sync(0xffffu, bi,   o);
            if (v > best || (v == best && j < bi)) { best = v; bi = j; }
        }
        if (t == 0) {
            g_pv[buf * GRID + blockIdx.x] = best;
            g_pi[buf * GRID + blockIdx.x] = bi;
        }
    }
    __syncthreads();   // sv/si reused by later phases
}

// spread low 16 bits of x into even bit positions
__device__ __forceinline__ unsigned expand16(unsigned x) {
    x &= 0xFFFFu;
    x = (x | (x << 8)) & 0x00FF00FFu;
    x = (x | (x << 4)) & 0x0F0F0F0Fu;
    x = (x | (x << 2)) & 0x33333333u;
    x = (x | (x << 1)) & 0x55555555u;
    return x;
}

// kept-rank k -> source point index, via per-quarter staging regions
__device__ __forceinline__ int rank_lookup(const int* stg, int k,
                                           int c1, int c2, int c3) {
    const int qq  = (k >= c1) + (k >= c2) + (k >= c3);
    const int cum = (qq == 0) ? 0 : (qq == 1) ? c1 : (qq == 2) ? c2 : c3;
    return stg[qq * QN + (k - cum)];
}

__global__ __launch_bounds__(TH, 2) void mega_kernel(const float* __restrict__ pts,
                                                     float* __restrict__ out) {
    const int cta  = blockIdx.x;
    const int b    = cta / CPB;
    const int q    = cta % CPB;
    const int base = q * QN;                         // batch-local start
    const float* P = pts + (size_t)b * N * 6;
    const float4* In = (const float4*)P;             // batch rows as float4s
    const int t = threadIdx.x;
    const int lane = t & 31, w = t >> 5;

    __shared__ float4   sc[4];
    __shared__ float    sv[16];
    __shared__ int      si[16];
    __shared__ int      swarp[16];
    __shared__ int      sq[CPB];
    __shared__ unsigned sw[WQ];                      // mask words (2 KB)

    // ===== Phase 0: pair-pack -> XY4/Z2 scratch + dist^2 to center 0 =======
    const float c0x = P[0], c0y = P[1], c0z = P[2];  // center 0 = point 0
    if (t == 0) sc[0] = make_float4(c0x, c0y, c0z, 0.f);
    {
        float best = -1.0f; int bi = 0;
        #pragma unroll 4
        for (int k = 0; k < PPAIR; k++) {
            const int pr = q * QP + t + k * TH;      // batch-local pair
            const int gp = b * (N / 2) + pr;         // global pair id
            const float4 f0 = In[pr * 3];            // x0 y0 z0 a0
            const float4 f1 = In[pr * 3 + 1];        // b0 c0 x1 y1
            const float4 f2 = In[pr * 3 + 2];        // z1 a1 b1 c1
            g_xy4[gp] = make_float4(f0.x, f0.y, f1.z, f1.w);
            g_z2[gp]  = make_float2(f0.z, f2.x);
            float dx = f0.x - c0x, dy = f0.y - c0y, dz = f0.z - c0z;
            const float md0 = dx * dx + dy * dy + dz * dz;
            dx = f1.z - c0x; dy = f1.w - c0y; dz = f2.x - c0z;
            const float md1 = dx * dx + dy * dy + dz * dz;
            const int gi = b * N + pr * 2;
            if (md0 > best) { best = md0; bi = gi; }     // strict >: min-index ties
            if (md1 > best) { best = md1; bi = gi + 1; }
        }
        block_partial(best, bi, /*buf=*/0, sv, si);
    }
    batch_sync(b);

    // ========== Phases 1,2: FPS steps; s==3 only resolves center 3 =========
    for (int s = 1; s <= 3; s++) {
        const int rbuf = (s - 1) & 1;                // buffer written by phase s-1
        if (t == 0) {
            float bv = g_pv[rbuf * GRID + b * CPB];
            int   bj = g_pi[rbuf * GRID + b * CPB];
            #pragma unroll
            for (int i = 1; i < CPB; i++) {
                const float v = g_pv[rbuf * GRID + b * CPB + i];
                const int   j = g_pi[rbuf * GRID + b * CPB + i];
                if (v > bv || (v == bv && j < bj)) { bv = v; bj = j; }
            }
            const float* cp = pts + (size_t)bj * 6;  // xyz of chosen point
            sc[s] = make_float4(cp[0], cp[1], cp[2], 0.f);
        }
        __syncthreads();
        if (s == 3) break;                           // all 4 centers known

        float best = -1.0f; int bi = 0;
        #pragma unroll 4
        for (int k = 0; k < PPAIR; k++) {
            const int pr = q * QP + t + k * TH;
            const int gp = b * (N / 2) + pr;
            const float4 xy = g_xy4[gp];             // 1 LDG.128 per pair
            const float2 zz = g_z2[gp];              // 1 LDG.64 per pair
            float md0 = 1e10f, md1 = 1e10f;
            for (int cc = 0; cc <= s; cc++) {
                float dx = xy.x - sc[cc].x, dy = xy.y - sc[cc].y, dz = zz.x - sc[cc].z;
                md0 = fminf(md0, dx * dx + dy * dy + dz * dz);
                dx = xy.z - sc[cc].x; dy = xy.w - sc[cc].y; dz = zz.y - sc[cc].z;
                md1 = fminf(md1, dx * dx + dy * dy + dz * dz);
            }
            const int gi = b * N + pr * 2;
            if (md0 > best) { best = md0; bi = gi; }
            if (md1 > best) { best = md1; bi = gi + 1; }
        }
        block_partial(best, bi, /*buf=*/s & 1, sv, si);
        batch_sync(b);
    }

    // ====== Phase 3: keep bitmask -> smem words (paired, bit-interleave) ===
    {
        const float4 cc0 = sc[0], cc1 = sc[1], cc2 = sc[2], cc3 = sc[3];
        #pragma unroll 4
        for (int k = 0; k < PPAIR; k++) {
            const int pr = q * QP + t + k * TH;      // lanes consecutive pairs
            const int gp = b * (N / 2) + pr;
            const float4 xy = g_xy4[gp];
            const float2 zz = g_z2[gp];
            float dx = xy.x - cc0.x, dy = xy.y - cc0.y, dz = zz.x - cc0.z;
            float md0 = fminf(1e10f, dx * dx + dy * dy + dz * dz);
            dx = xy.x - cc1.x; dy = xy.y - cc1.y; dz = zz.x - cc1.z;
            md0 = fminf(md0, dx * dx + dy * dy + dz * dz);
            dx = xy.x - cc2.x; dy = xy.y - cc2.y; dz = zz.x - cc2.z;
            md0 = fminf(md0, dx * dx + dy * dy + dz * dz);
            dx = xy.x - cc3.x; dy = xy.y - cc3.y; dz = zz.x - cc3.z;
            md0 = fminf(md0, dx * dx + dy * dy + dz * dz);

            dx = xy.z - cc0.x; dy = xy.w - cc0.y; dz = zz.y - cc0.z;
            float md1 = fminf(1e10f, dx * dx + dy * dy + dz * dz);
            dx = xy.z - cc1.x; dy = xy.w - cc1.y; dz = zz.y - cc1.z;
            md1 = fminf(md1, dx * dx + dy * dy + dz * dz);
            dx = xy.z - cc2.x; dy = xy.w - cc2.y; dz = zz.y - cc2.z;
            md1 = fminf(md1, dx * dx + dy * dy + dz * dz);
            dx = xy.z - cc3.x; dy = xy.w - cc3.y; dz = zz.y - cc3.z;
            md1 = fminf(md1, dx * dx + dy * dy + dz * dz);

            const unsigned b0 = __ballot_sync(0xffffffffu, __fsqrt_rn(md0) >= 0.2f);
            const unsigned b1 = __ballot_sync(0xffffffffu, __fsqrt_rn(md1) >= 0.2f);
            // warp covers 64 consecutive points -> 2 words, bit-interleaved
            const int wq0 = 2 * w + k * 32;                  // quarter-local word id
            if (lane == 0) sw[wq0]     = expand16(b0) | (expand16(b1) << 1);
            if (lane == 1) sw[wq0 + 1] = expand16(b0 >> 16) | (expand16(b1 >> 16) << 1);
        }
    }
    __syncthreads();                                  // block-local only

    // == Phase 4: quarter-local stable compaction into this CTA's stage region
    int nv, c1, c2, c3;                              // cumulative quarter starts
    {
        const unsigned wd = sw[t];                   // word t of this quarter
        const int cnt = __popc(wd);

        int inc = cnt;
        #pragma unroll
        for (int o = 1; o < 32; o <<= 1) {
            const int u = __shfl_up_sync(0xffffffffu, inc, o);
            if (lane >= o) inc += u;
        }
        if (lane == 31) swarp[w] = inc;
        __syncthreads();
        if (t < 16) {
            int v2 = swarp[t];
            #pragma unroll
            for (int o = 1; o < 16; o <<= 1) {
                const int u = __shfl_up_sync(0xffffu, v2, o);
                if (t >= o) v2 += u;
            }
            swarp[t] = v2;
        }
        __syncthreads();
        const int off_local = inc - cnt + (w ? swarp[w - 1] : 0);
        if (t == 0) g_qtot[cta] = swarp[15];         // publish quarter total

        // write kept indices into this CTA's own region (overlaps barrier)
        int* stq = g_stage + b * N + q * QN;
        int pos = off_local;
        const int pbase = q * QN + t * 32;           // first point of this word
        unsigned m = wd;
        while (m) { const int l2 = __ffs(m) - 1; m &= m - 1; stq[pos++] = pbase + l2; }

        batch_sync(b);                               // stage + qtot visible

        if (t < CPB) sq[t] = g_qtot[b * CPB + t];
        __syncthreads();
        c1 = sq[0]; c2 = c1 + sq[1]; c3 = c2 + sq[2];
        nv = c3 + sq[3];
    }

    // ====== Phase 5: gather; incremental modulo + consecutive-run fast path =
    {
        const int* stg = g_stage + (b << 16);
        const bool incr_ok = (nv > 1088);            // TH*2 + 64 bound
        // warp's kept-rank for its first row, maintained incrementally
        int kf = 0;
        if (incr_ok) kf = (base + w * 64) % nv;
        const int step = incr_ok ? (TH * 2) % nv : 0;

        #pragma unroll 2
        for (int k = 0; k < PPT / 2; k++) {
            const int jr0 = base + (w * 32 + k * TH) * 2;   // warp's first row (64 rows)
            int kf_cur;
            if (incr_ok) {
                kf_cur = kf;
                kf += step; if (kf >= nv) kf -= nv;         // next iteration
            } else {
                kf_cur = (nv > 0) ? jr0 % nv : 0;
            }
            bool fast = false; int sfirst = 0;
            if (nv > 0 && kf_cur + 63 < nv) {
                int sA = 0, sB = 0;
                if (lane == 0) {
                    sA = rank_lookup(stg, kf_cur,      c1, c2, c3);
                    sB = rank_lookup(stg, kf_cur + 63, c1, c2, c3);
                }
                sA = __shfl_sync(0xffffffffu, sA, 0);
                sB = __shfl_sync(0xffffffffu, sB, 0);
                fast = (sB - sA == 63);               // 64 consecutive sources
                sfirst = sA;
            }
            if (fast) {
                // contiguous 1536B block copy, fully coalesced float2s
                const float2* s2 = (const float2*)(pts + ((size_t)(b << 16) + sfirst) * 6);
                float2* d2 = (float2*)(out + ((size_t)b * N + jr0) * 6);
                #pragma unroll
                for (int m = 0; m < 6; m++) __stcs(&d2[m * 32 + lane], s2[m * 32 + lane]);
            } else {
                const int jr = jr0 + lane * 2;              // this lane's 2 rows
                float4* dst = (float4*)(out + ((size_t)b * N + jr) * 6);
                if (nv == 0) {
                    const float4 z4 = make_float4(0.f, 0.f, 0.f, 0.f);
                    __stcs(&dst[0], z4); __stcs(&dst[1], z4); __stcs(&dst[2], z4);
                    continue;
                }
                int k0;
                if (incr_ok) { k0 = kf_cur + lane * 2; if (k0 >= nv) k0 -= nv; }
                else         { k0 = jr % nv; }
                const int k1 = (k0 + 1 == nv) ? 0 : k0 + 1;
                const int s0 = rank_lookup(stg, k0, c1, c2, c3);
                const int s1 = rank_lookup(stg, k1, c1, c2, c3);
                const float* p0 = pts + ((size_t)(b << 16) + s0) * 6;
                const float* p1 = pts + ((size_t)(b << 16) + s1) * 6;
                const float2 a0 = *(const float2*)p0;
                const float2 a1 = *(const float2*)(p0 + 2);
                const float2 a2 = *(const float2*)(p0 + 4);
                const float2 b0 = *(const float2*)p1;
                const float2 b1 = *(const float2*)(p1 + 2);
                const float2 b2 = *(const float2*)(p1 + 4);
                __stcs(&dst[0], make_float4(a0.x, a0.y, a1.x, a1.y));
                __stcs(&dst[1], make_float4(a2.x, a2.y, b0.x, b0.y));
                __stcs(&dst[2], make_float4(b1.x, b1.y, b2.x, b2.y));
            }
        }
    }
}

extern "C" void kernel_launch(void* const* d_in, const int* in_sizes, int n_in,
                              void* d_out, int out_size) {
    const float* pts = (const float*)d_in[0];
    float* out = (float*)d_out;
    mega_kernel<<<GRID, TH>>>(pts, out);
}